// round 12
// baseline (speedup 1.0000x reference)
#include <cuda_runtime.h>
#include <stdint.h>

#define BATCH 32
#define NPTS  16384
#define NROT  24
#define IMS   64
#define NPIX  4096
#define NIMG  768
#define TOT   (NIMG * NPIX)            // 3,145,728
#define NBUCK 65                       // 64 py rows + 1 py-OOR bucket
#define CAP   1024                     // max real bucket ~530

// Winner keys (p+1). max key <=> max n within a batch <=> last-write-wins.
// Zero-initialized at load; unpack resets everything each call.
__device__ __align__(16) unsigned g_win[TOT];      // 12.6 MB, L2-resident
__device__ unsigned g_cnt[BATCH * NBUCK];
__device__ unsigned g_buck[BATCH * NBUCK * CAP];   // point ids

// ---------------------------------------------------------------- kernel 1
// Bucket points by (batch, py). py is rotation-invariant (rotation about y).
__global__ __launch_bounds__(256) void bucket_kernel(const float* __restrict__ xyz)
{
    __shared__ unsigned scnt[NBUCK], sbase[NBUCK];
    int tid = threadIdx.x;
    if (tid < NBUCK) scnt[tid] = 0u;
    __syncthreads();

    int p = blockIdx.x * 256 + tid;     // block lies within one batch
    int b = p >> 14;
    float y = xyz[p * 3 + 1];
    int py = __float2int_rn(fmaf(y, 16.0f, 32.0f));  // == rn((y+2)/0.0625), exact
    int bk = ((unsigned)py < IMS) ? py : 64;         // OOR py -> bucket 64
    unsigned rank = atomicAdd(&scnt[bk], 1u);
    __syncthreads();

    if (tid < NBUCK && scnt[tid])
        sbase[tid] = atomicAdd(&g_cnt[b * NBUCK + tid], scnt[tid]);
    __syncthreads();

    g_buck[(b * NBUCK + bk) * CAP + sbase[bk] + rank] = (unsigned)p;
}

// ---------------------------------------------------------------- kernel 2
// One CTA per (batch, bucket), LPT-ordered: biggest (center) rows first.
// All lanes of a warp share py; same-pixel lanes are deduped pre-atomic via
// match_any + reduce_max, so each distinct pixel gets exactly one REDG lane.
__global__ __launch_bounds__(256) void scatter_kernel(const float* __restrict__ xyz,
                                                      const float* __restrict__ rot)
{
    __shared__ float2 srot[NROT];   // (m00, m02) = (c, -s)
    __shared__ unsigned s_red[8];
    int tid = threadIdx.x;
    int lane = tid & 31;
    if (tid < NROT) {
        const float* m = rot + tid * 9;
        srot[tid] = make_float2(m[0], m[2]);
    }
    __syncthreads();

    int bid = blockIdx.x;
    int b, bk;
    if (bid < BATCH * IMS) {
        b = bid & 31;                               // 32 same-size CTAs adjacent
        int i = bid >> 5;                           // centrality rank 0..63
        bk = (i & 1) ? (32 - ((i + 1) >> 1)) : (32 + (i >> 1));
    } else {
        b = bid - BATCH * IMS;                      // py-OOR buckets last
        bk = 64;
    }

    unsigned cnt = g_cnt[b * NBUCK + bk];
    const unsigned* __restrict__ buck = g_buck + (size_t)(b * NBUCK + bk) * CAP;
    unsigned* __restrict__ wbase = g_win + (size_t)b * NROT * NPIX;

    if (bk == 64) {
        // py-OOR: masked in every rotation -> pixel (0,0) of all 24 images.
        unsigned best = 0u;
        for (unsigned i = tid; i < cnt; i += 256) best = max(best, buck[i] + 1u);
        best = __reduce_max_sync(0xffffffffu, best);
        if (lane == 0) s_red[tid >> 5] = best;
        __syncthreads();
        if (tid < NROT) {
            unsigned m = s_red[0];
#pragma unroll
            for (int j = 1; j < 8; j++) m = max(m, s_red[j]);
            if (m) atomicMax(wbase + tid * NPIX, m);
        }
        return;
    }

    int rowoff = bk * IMS;
    unsigned cnt_pad = (cnt + 255u) & ~255u;   // uniform trips: warps stay converged
    for (unsigned i = tid; i < cnt_pad; i += 256) {
        bool act = i < cnt;
        unsigned p = act ? buck[i] : 0u;
        unsigned key = act ? (p + 1u) : 0u;    // key 0 never wins a max
        float x = act ? xyz[p * 3 + 0] : 0.0f;
        float z = act ? xyz[p * 3 + 2] : 0.0f;
#pragma unroll
        for (int r = 0; r < NROT; r++) {
            float2 m = srot[r];
            float xr = fmaf(m.y, z, m.x * x);              // matches XLA fma; 0*y exact
            int px = __float2int_rn(fmaf(xr, 16.0f, 32.0f)); // == rn((xr+2)*16)
            // px-OOR and inactive lanes fold into the pixel-0 group (key 0 or
            // genuine masked writes -> pixel 0, exactly as the reference).
            int pix = (act & ((unsigned)px < IMS)) ? (rowoff + px) : 0;
            unsigned mm = __match_any_sync(0xffffffffu, pix);
            unsigned gk = __reduce_max_sync(mm, key);      // group winner
            if (lane == __ffs(mm) - 1 && gk)               // one lane per pixel
                atomicMax(wbase + r * NPIX + pix, gk);
        }
    }
}

// ---------------------------------------------------------------- kernel 3
// 4 pixels per thread: uint4 winner load + reset, float4 output store.
__global__ __launch_bounds__(256) void unpack_kernel(const float* __restrict__ xyz,
                                                     const float* __restrict__ rot,
                                                     float* __restrict__ out)
{
    int t = blockIdx.x * 256 + threadIdx.x;   // [0, TOT/4)
    int i = t * 4;
    uint4 w4 = *reinterpret_cast<uint4*>(g_win + i);
    *reinterpret_cast<uint4*>(g_win + i) = make_uint4(0u, 0u, 0u, 0u);
    if (t < BATCH * NBUCK) g_cnt[t] = 0u;

    int img = i >> 12;                        // 4 consecutive pixels share image
    int r = img - (img / NROT) * NROT;
    float m20 = rot[r * 9 + 6];
    float m22 = rot[r * 9 + 8];

    unsigned wk[4] = {w4.x, w4.y, w4.z, w4.w};
    float v[4];
#pragma unroll
    for (int j = 0; j < 4; j++) {
        float val = 0.0f;
        unsigned w = wk[j];
        if (w) {
            unsigned p = w - 1u;
            float x = xyz[p * 3 + 0];
            float z = xyz[p * 3 + 2];
            float zr = fmaf(m22, z, m20 * x);
            // Exact RN /10: zr/10 is never a float rounding midpoint, so the
            // double product rounds to the correctly-rounded float quotient.
            val = (float)((double)zr * 0.1);
        }
        v[j] = val;
    }
    *reinterpret_cast<float4*>(out + i) = make_float4(v[0], v[1], v[2], v[3]);
}

extern "C" void kernel_launch(void* const* d_in, const int* in_sizes, int n_in,
                              void* d_out, int out_size)
{
    const float* xyz = (const float*)d_in[0];   // [32, 16384, 3] f32
    const float* rot = (const float*)d_in[1];   // [24, 3, 3] f32
    float* out = (float*)d_out;                 // [32, 24, 64, 64] f32

    bucket_kernel<<<(BATCH * NPTS) / 256, 256>>>(xyz);
    scatter_kernel<<<BATCH * NBUCK, 256>>>(xyz, rot);
    unpack_kernel<<<TOT / 4 / 256, 256>>>(xyz, rot, out);
}

// round 14
// speedup vs baseline: 3.1672x; 3.1672x over previous
#include <cuda_runtime.h>
#include <stdint.h>

#define BATCH 32
#define NPTS  16384
#define NROT  24
#define IMS   64
#define NPIX  4096
#define NIMG  768
#define TOT   (NIMG * NPIX)            // 3,145,728
#define NBUCK 65                       // 64 py rows + 1 py-OOR bucket
#define CAP   1024                     // max real bucket ~530
#define HALVES 2                       // CTAs per row bucket

// Winner keys (p+1). max key <=> max n within a batch <=> last-write-wins.
// Zero-initialized at load; unpack resets everything each call.
__device__ __align__(16) unsigned g_win[TOT];      // 12.6 MB, L2-resident
__device__ unsigned g_cnt[BATCH * NBUCK];
__device__ unsigned g_buck[BATCH * NBUCK * CAP];   // point ids

// ---------------------------------------------------------------- kernel 1
// Bucket points by (batch, py). py is rotation-invariant (rotation about y).
__global__ __launch_bounds__(256) void bucket_kernel(const float* __restrict__ xyz)
{
    __shared__ unsigned scnt[NBUCK], sbase[NBUCK];
    int tid = threadIdx.x;
    if (tid < NBUCK) scnt[tid] = 0u;
    __syncthreads();

    int p = blockIdx.x * 256 + tid;     // block lies within one batch
    int b = p >> 14;
    float y = xyz[p * 3 + 1];
    int py = __float2int_rn(fmaf(y, 16.0f, 32.0f));  // == rn((y+2)/0.0625), exact
    int bk = ((unsigned)py < IMS) ? py : 64;         // OOR py -> bucket 64
    unsigned rank = atomicAdd(&scnt[bk], 1u);
    __syncthreads();

    if (tid < NBUCK && scnt[tid])
        sbase[tid] = atomicAdd(&g_cnt[b * NBUCK + tid], scnt[tid]);
    __syncthreads();

    g_buck[(b * NBUCK + bk) * CAP + sbase[bk] + rank] = (unsigned)p;
}

// ---------------------------------------------------------------- kernel 2
// HALVES CTAs per (batch, row-bucket), LPT-ordered: biggest (center) rows
// first, both halves of a bucket at the same rank. All lanes of a warp share
// py -> each rotation's 32 atomics hit one aligned 256B image row.
__global__ __launch_bounds__(256) void scatter_kernel(const float* __restrict__ xyz,
                                                      const float* __restrict__ rot)
{
    __shared__ float2 srot[NROT];   // (m00, m02) = (c, -s)
    __shared__ unsigned s_red[8];
    int tid = threadIdx.x;
    if (tid < NROT) {
        const float* m = rot + tid * 9;
        srot[tid] = make_float2(m[0], m[2]);
    }
    __syncthreads();

    int bid = blockIdx.x;
    int b, bk, half;
    if (bid < BATCH * IMS * HALVES) {
        half = bid & 1;
        int q = bid >> 1;
        b = q & 31;                                 // 32 same-size CTAs adjacent
        int i = q >> 5;                             // centrality rank 0..63
        bk = (i & 1) ? (32 - ((i + 1) >> 1)) : (32 + (i >> 1));
    } else {
        b = bid - BATCH * IMS * HALVES;             // py-OOR buckets last
        bk = 64;
        half = 0;
    }

    unsigned cnt = g_cnt[b * NBUCK + bk];
    const unsigned* __restrict__ buck = g_buck + (size_t)(b * NBUCK + bk) * CAP;
    unsigned* __restrict__ wbase = g_win + (size_t)b * NROT * NPIX;

    if (bk == 64) {
        // py-OOR: masked in every rotation -> pixel (0,0) of all 24 images.
        // Only the max key can win; block-reduce then 24 atomics total.
        unsigned best = 0u;
        for (unsigned i = tid; i < cnt; i += 256) best = max(best, buck[i] + 1u);
        best = __reduce_max_sync(0xffffffffu, best);
        if ((tid & 31) == 0) s_red[tid >> 5] = best;
        __syncthreads();
        if (tid < NROT) {
            unsigned m = s_red[0];
#pragma unroll
            for (int j = 1; j < 8; j++) m = max(m, s_red[j]);
            if (m) atomicMax(wbase + tid * NPIX, m);
        }
        return;
    }

    int rowoff = bk * IMS;
    for (unsigned i = half * 256 + tid; i < cnt; i += 256 * HALVES) {
        unsigned p = buck[i];
        unsigned key = p + 1u;
        float x = xyz[p * 3 + 0];
        float z = xyz[p * 3 + 2];
#pragma unroll
        for (int r = 0; r < NROT; r++) {
            float2 m = srot[r];
            float xr = fmaf(m.y, z, m.x * x);            // matches XLA fma; 0*y exact
            int px = __float2int_rn(fmaf(xr, 16.0f, 32.0f)); // == rn((xr+2)*16)
            int pix = ((unsigned)px < IMS) ? (rowoff + px) : 0; // px-OOR -> pixel 0
            atomicMax(wbase + r * NPIX + pix, key);
        }
    }
}

// ---------------------------------------------------------------- kernel 3
// 4 pixels per thread: uint4 winner load + reset, float4 output store.
// Winner key -> gather (x,z), recompute val with bit-identical FP sequence.
__global__ __launch_bounds__(256) void unpack_kernel(const float* __restrict__ xyz,
                                                     const float* __restrict__ rot,
                                                     float* __restrict__ out)
{
    int t = blockIdx.x * 256 + threadIdx.x;   // [0, TOT/4)
    int i = t * 4;
    uint4 w4 = *reinterpret_cast<uint4*>(g_win + i);
    *reinterpret_cast<uint4*>(g_win + i) = make_uint4(0u, 0u, 0u, 0u);
    if (t < BATCH * NBUCK) g_cnt[t] = 0u;

    int img = i >> 12;                        // 4 consecutive pixels share image
    int r = img - (img / NROT) * NROT;
    float m20 = rot[r * 9 + 6];
    float m22 = rot[r * 9 + 8];

    unsigned wk[4] = {w4.x, w4.y, w4.z, w4.w};
    float v[4];
#pragma unroll
    for (int j = 0; j < 4; j++) {
        float val = 0.0f;
        unsigned w = wk[j];
        if (w) {
            unsigned p = w - 1u;
            float x = xyz[p * 3 + 0];
            float z = xyz[p * 3 + 2];
            float zr = fmaf(m22, z, m20 * x);
            // Exact RN /10: zr/10 is never a float rounding midpoint, so the
            // double product rounds to the correctly-rounded float quotient.
            val = (float)((double)zr * 0.1);
        }
        v[j] = val;
    }
    *reinterpret_cast<float4*>(out + i) = make_float4(v[0], v[1], v[2], v[3]);
}

extern "C" void kernel_launch(void* const* d_in, const int* in_sizes, int n_in,
                              void* d_out, int out_size)
{
    const float* xyz = (const float*)d_in[0];   // [32, 16384, 3] f32
    const float* rot = (const float*)d_in[1];   // [24, 3, 3] f32
    float* out = (float*)d_out;                 // [32, 24, 64, 64] f32

    bucket_kernel<<<(BATCH * NPTS) / 256, 256>>>(xyz);
    scatter_kernel<<<BATCH * IMS * HALVES + BATCH, 256>>>(xyz, rot);
    unpack_kernel<<<TOT / 4 / 256, 256>>>(xyz, rot, out);
}